// round 1
// baseline (speedup 1.0000x reference)
#include <cuda_runtime.h>
#include <cuda_bf16.h>
#include <cstddef>

#define NN 100000

// ---------------- scratch (static __device__, no allocation) ----------------
__device__ __align__(256) float g_agg1[NN * 128];
__device__ __align__(256) float g_X1[(size_t)NN * 256];
__device__ __align__(256) float g_T2[NN * 128];
__device__ __align__(256) float g_agg2[NN * 128];
__device__ __align__(256) float g_X2[NN * 128];
__device__ __align__(256) float g_T3[NN * 40];
__device__ __align__(256) float g_agg3[NN * 40];
__device__ __align__(256) float g_outdeg[NN];
__device__ __align__(256) float g_indeg[NN];
__device__ __align__(256) float g_invout[NN];
__device__ __align__(256) float g_invin[NN];

// ---------------- small kernels ----------------
__global__ void zero_kernel(float* __restrict__ p, int n) {
    int i = blockIdx.x * blockDim.x + threadIdx.x;
    if (i < n) p[i] = 0.0f;
}

__global__ void degree_kernel(const int* __restrict__ src, const int* __restrict__ dst,
                              float* __restrict__ outdeg, float* __restrict__ indeg, int E) {
    int i = blockIdx.x * blockDim.x + threadIdx.x;
    if (i >= E) return;
    atomicAdd(&outdeg[src[i]], 1.0f);
    atomicAdd(&indeg[dst[i]], 1.0f);
}

__global__ void inv_kernel(const float* __restrict__ outdeg, const float* __restrict__ indeg,
                           float* __restrict__ invout, float* __restrict__ invin, int n) {
    int i = blockIdx.x * blockDim.x + threadIdx.x;
    if (i >= n) return;
    invout[i] = rsqrtf(fmaxf(outdeg[i], 1.0f));
    invin[i]  = rsqrtf(fmaxf(indeg[i], 1.0f));
}

// out[m][.] = (relu?) (agg[m][.] * invin[m] + bias[.])
__global__ void ew_post_kernel(const float* __restrict__ agg, const float* __restrict__ invin,
                               const float* __restrict__ bias, float* __restrict__ out,
                               int M, int F4, int relu) {
    int i = blockIdx.x * blockDim.x + threadIdx.x;
    if (i >= M * F4) return;
    int m = i / F4;
    int c = i % F4;
    float4 v = reinterpret_cast<const float4*>(agg)[i];
    float4 b = reinterpret_cast<const float4*>(bias)[c];
    float s = invin[m];
    v.x = v.x * s + b.x;
    v.y = v.y * s + b.y;
    v.z = v.z * s + b.z;
    v.w = v.w * s + b.w;
    if (relu) {
        v.x = fmaxf(v.x, 0.f); v.y = fmaxf(v.y, 0.f);
        v.z = fmaxf(v.z, 0.f); v.w = fmaxf(v.w, 0.f);
    }
    reinterpret_cast<float4*>(out)[i] = v;
}

// ---------------- edge scatter (vectorized RED, sm_90+) ----------------
__device__ __forceinline__ void red_add_v4(float* ptr, float4 v) {
    asm volatile("red.global.add.v4.f32 [%0], {%1, %2, %3, %4};"
                 :: "l"(ptr), "f"(v.x), "f"(v.y), "f"(v.z), "f"(v.w)
                 : "memory");
}

template <int F4>
__global__ void scatter_kernel(const float* __restrict__ H, const int* __restrict__ src,
                               const int* __restrict__ dst, float* __restrict__ agg,
                               int E, const float* __restrict__ pre) {
    int i = blockIdx.x * blockDim.x + threadIdx.x;
    if (i >= E * F4) return;
    int e = i / F4;
    int c = i % F4;
    int s = src[e];
    int d = dst[e];
    float4 v = reinterpret_cast<const float4*>(H)[(size_t)s * F4 + c];
    if (pre) {
        float p = pre[s];
        v.x *= p; v.y *= p; v.z *= p; v.w *= p;
    }
    red_add_v4(agg + ((size_t)d * F4 + c) * 4, v);
}

// ---------------- SGEMM: C[M,N] = (pre? diag(pre):I) A[M,K] @ W[K,N], epilogue ----------------
constexpr int BM = 128, BN = 128, BK = 8, TM = 8, TN = 8;

template <bool PRE, bool POST, bool RELU>
__global__ __launch_bounds__(256)
void sgemm_kernel(const float* __restrict__ A, const float* __restrict__ W,
                  float* __restrict__ C, int M, int N, int K,
                  const float* __restrict__ pre, const float* __restrict__ post,
                  const float* __restrict__ bias) {
    __shared__ float As[BK][BM];
    __shared__ float Ws[BK][BN + 4];

    const int tid = threadIdx.x;          // 256 threads
    const int m0 = blockIdx.x * BM;
    const int n0 = blockIdx.y * BN;
    const int ty = tid >> 4;               // 0..15
    const int tx = tid & 15;               // 0..15

    const int ar = tid >> 1;               // 0..127  (A tile row)
    const int ak = (tid & 1) * 4;          // 0 or 4  (A tile k, float4)
    const int wk = tid >> 5;               // 0..7    (W tile k)
    const int wn = (tid & 31) * 4;         // 0..124  (W tile n, float4)

    float ps = 1.0f;
    if (PRE) {
        int r = m0 + ar;
        ps = (r < M) ? pre[r] : 0.0f;
    }

    float acc[TM][TN] = {};

    for (int k0 = 0; k0 < K; k0 += BK) {
        // load A tile (BM x BK), store transposed
        float4 a = make_float4(0.f, 0.f, 0.f, 0.f);
        {
            int r = m0 + ar;
            if (r < M)
                a = *reinterpret_cast<const float4*>(A + (size_t)r * K + (k0 + ak));
            if (PRE) { a.x *= ps; a.y *= ps; a.z *= ps; a.w *= ps; }
            As[ak + 0][ar] = a.x;
            As[ak + 1][ar] = a.y;
            As[ak + 2][ar] = a.z;
            As[ak + 3][ar] = a.w;
        }
        // load W tile (BK x BN)
        {
            float4 w = make_float4(0.f, 0.f, 0.f, 0.f);
            int col = n0 + wn;
            if (col < N)
                w = *reinterpret_cast<const float4*>(W + (size_t)(k0 + wk) * N + col);
            Ws[wk][wn + 0] = w.x;
            Ws[wk][wn + 1] = w.y;
            Ws[wk][wn + 2] = w.z;
            Ws[wk][wn + 3] = w.w;
        }
        __syncthreads();

        #pragma unroll
        for (int kk = 0; kk < BK; kk++) {
            float av[TM], wv[TN];
            *reinterpret_cast<float4*>(&av[0]) = *reinterpret_cast<const float4*>(&As[kk][ty * TM]);
            *reinterpret_cast<float4*>(&av[4]) = *reinterpret_cast<const float4*>(&As[kk][ty * TM + 4]);
            *reinterpret_cast<float4*>(&wv[0]) = *reinterpret_cast<const float4*>(&Ws[kk][tx * TN]);
            *reinterpret_cast<float4*>(&wv[4]) = *reinterpret_cast<const float4*>(&Ws[kk][tx * TN + 4]);
            #pragma unroll
            for (int i = 0; i < TM; i++)
                #pragma unroll
                for (int j = 0; j < TN; j++)
                    acc[i][j] = fmaf(av[i], wv[j], acc[i][j]);
        }
        __syncthreads();
    }

    #pragma unroll
    for (int i = 0; i < TM; i++) {
        int r = m0 + ty * TM + i;
        if (r >= M) continue;
        float pr = POST ? post[r] : 1.0f;
        #pragma unroll
        for (int j = 0; j < TN; j++) {
            int col = n0 + tx * TN + j;
            if (col >= N) continue;
            float c = acc[i][j];
            if (POST) c = c * pr + bias[col];
            if (RELU) c = fmaxf(c, 0.0f);
            C[(size_t)r * N + col] = c;
        }
    }
}

// ---------------- launch ----------------
static inline int cdiv(int a, int b) { return (a + b - 1) / b; }

extern "C" void kernel_launch(void* const* d_in, const int* in_sizes, int n_in,
                              void* d_out, int out_size) {
    const float* feat = (const float*)d_in[0];   // [NN,128]
    const int*   src  = (const int*)d_in[1];     // [E]
    const int*   dst  = (const int*)d_in[2];     // [E]
    const float* W1   = (const float*)d_in[3];   // [128,256]
    const float* b1   = (const float*)d_in[4];   // [256]
    const float* W2   = (const float*)d_in[5];   // [256,128]
    const float* b2   = (const float*)d_in[6];   // [128]
    const float* W3   = (const float*)d_in[7];   // [128,40]
    const float* b3   = (const float*)d_in[8];   // [40]
    const int E = in_sizes[1];
    float* out = (float*)d_out;

    float *agg1, *X1, *T2, *agg2, *X2, *T3, *agg3, *outdeg, *indeg, *invout, *invin;
    cudaGetSymbolAddress((void**)&agg1, g_agg1);
    cudaGetSymbolAddress((void**)&X1, g_X1);
    cudaGetSymbolAddress((void**)&T2, g_T2);
    cudaGetSymbolAddress((void**)&agg2, g_agg2);
    cudaGetSymbolAddress((void**)&X2, g_X2);
    cudaGetSymbolAddress((void**)&T3, g_T3);
    cudaGetSymbolAddress((void**)&agg3, g_agg3);
    cudaGetSymbolAddress((void**)&outdeg, g_outdeg);
    cudaGetSymbolAddress((void**)&indeg, g_indeg);
    cudaGetSymbolAddress((void**)&invout, g_invout);
    cudaGetSymbolAddress((void**)&invin, g_invin);

    const int T = 256;

    // zero accumulators + degrees
    zero_kernel<<<cdiv(NN * 128, T), T>>>(agg1, NN * 128);
    zero_kernel<<<cdiv(NN * 128, T), T>>>(agg2, NN * 128);
    zero_kernel<<<cdiv(NN * 40, T), T>>>(agg3, NN * 40);
    zero_kernel<<<cdiv(NN, T), T>>>(outdeg, NN);
    zero_kernel<<<cdiv(NN, T), T>>>(indeg, NN);

    // degree norms
    degree_kernel<<<cdiv(E, T), T>>>(src, dst, outdeg, indeg, E);
    inv_kernel<<<cdiv(NN, T), T>>>(outdeg, indeg, invout, invin, NN);

    // ---- Layer 1: aggregate-first (in=128 <= out=256) ----
    scatter_kernel<32><<<cdiv(E * 32, T), T>>>(feat, src, dst, agg1, E, invout);
    {
        dim3 grid(cdiv(NN, BM), cdiv(256, BN));
        sgemm_kernel<false, true, true><<<grid, T>>>(agg1, W1, X1, NN, 256, 128,
                                                     nullptr, invin, b1);
    }

    // ---- Layer 2: transform-first (in=256 > out=128) ----
    {
        dim3 grid(cdiv(NN, BM), cdiv(128, BN));
        sgemm_kernel<true, false, false><<<grid, T>>>(X1, W2, T2, NN, 128, 256,
                                                      invout, nullptr, nullptr);
    }
    scatter_kernel<32><<<cdiv(E * 32, T), T>>>(T2, src, dst, agg2, E, nullptr);
    ew_post_kernel<<<cdiv(NN * 32, T), T>>>(agg2, invin, b2, X2, NN, 32, 1);

    // ---- Layer 3: transform-first (in=128 > out=40) ----
    {
        dim3 grid(cdiv(NN, BM), cdiv(40, BN));
        sgemm_kernel<true, false, false><<<grid, T>>>(X2, W3, T3, NN, 40, 128,
                                                      invout, nullptr, nullptr);
    }
    scatter_kernel<10><<<cdiv(E * 10, T), T>>>(T3, src, dst, agg3, E, nullptr);
    ew_post_kernel<<<cdiv(NN * 10, T), T>>>(agg3, invin, b3, out, NN, 10, 0);
}

// round 3
// speedup vs baseline: 1.5889x; 1.5889x over previous
#include <cuda_runtime.h>
#include <cuda_bf16.h>
#include <cstdint>
#include <cstddef>

#define NN 100000

// ---------------- scratch (static __device__, no allocation) ----------------
__device__ __align__(256) float g_agg1[NN * 128];
__device__ __align__(256) float g_X1[(size_t)NN * 256];
__device__ __align__(256) float g_T2[NN * 128];
__device__ __align__(256) float g_agg2[NN * 128];
__device__ __align__(256) float g_X2[NN * 128];
__device__ __align__(256) float g_T3[NN * 40];
__device__ __align__(256) float g_agg3[NN * 40];
__device__ __align__(256) float g_outdeg[NN];
__device__ __align__(256) float g_indeg[NN];
__device__ __align__(256) float g_invout[NN];
__device__ __align__(256) float g_invin[NN];
// W^T split-bf16 (hi/lo), layout [N][K] K-contiguous
__device__ __align__(256) __nv_bfloat16 g_Wt1h[256 * 128];
__device__ __align__(256) __nv_bfloat16 g_Wt1l[256 * 128];
__device__ __align__(256) __nv_bfloat16 g_Wt2h[128 * 256];
__device__ __align__(256) __nv_bfloat16 g_Wt2l[128 * 256];
__device__ __align__(256) __nv_bfloat16 g_Wt3h[40 * 128];
__device__ __align__(256) __nv_bfloat16 g_Wt3l[40 * 128];

// ---------------- small kernels ----------------
__global__ void zero_all_kernel(float* __restrict__ a1, float* __restrict__ a2,
                                float* __restrict__ a3, float* __restrict__ d1,
                                float* __restrict__ d2) {
    int i = blockIdx.x * blockDim.x + threadIdx.x;
    if (i < NN * 128) { a1[i] = 0.0f; a2[i] = 0.0f; }
    if (i < NN * 40) a3[i] = 0.0f;
    if (i < NN) { d1[i] = 0.0f; d2[i] = 0.0f; }
}

__global__ void degree_kernel(const int* __restrict__ src, const int* __restrict__ dst,
                              float* __restrict__ outdeg, float* __restrict__ indeg, int E) {
    int i = blockIdx.x * blockDim.x + threadIdx.x;
    if (i >= E) return;
    atomicAdd(&outdeg[src[i]], 1.0f);
    atomicAdd(&indeg[dst[i]], 1.0f);
}

__global__ void inv_kernel(const float* __restrict__ outdeg, const float* __restrict__ indeg,
                           float* __restrict__ invout, float* __restrict__ invin, int n) {
    int i = blockIdx.x * blockDim.x + threadIdx.x;
    if (i >= n) return;
    invout[i] = rsqrtf(fmaxf(outdeg[i], 1.0f));
    invin[i]  = rsqrtf(fmaxf(indeg[i], 1.0f));
}

// W[K,N] fp32 -> W^T split bf16 [N][K]
__global__ void wsplit_kernel(const float* __restrict__ W, int K, int N,
                              __nv_bfloat16* __restrict__ th, __nv_bfloat16* __restrict__ tl) {
    int i = blockIdx.x * blockDim.x + threadIdx.x;
    if (i >= K * N) return;
    int k = i / N, n = i % N;
    float w = W[i];
    __nv_bfloat16 h = __float2bfloat16(w);
    float r = w - __bfloat162float(h);
    th[n * K + k] = h;
    tl[n * K + k] = __float2bfloat16(r);
}

__global__ void ew_post_kernel(const float* __restrict__ agg, const float* __restrict__ invin,
                               const float* __restrict__ bias, float* __restrict__ out,
                               int M, int F4, int relu) {
    int i = blockIdx.x * blockDim.x + threadIdx.x;
    if (i >= M * F4) return;
    int m = i / F4;
    int c = i % F4;
    float4 v = reinterpret_cast<const float4*>(agg)[i];
    float4 b = reinterpret_cast<const float4*>(bias)[c];
    float s = invin[m];
    v.x = v.x * s + b.x; v.y = v.y * s + b.y;
    v.z = v.z * s + b.z; v.w = v.w * s + b.w;
    if (relu) {
        v.x = fmaxf(v.x, 0.f); v.y = fmaxf(v.y, 0.f);
        v.z = fmaxf(v.z, 0.f); v.w = fmaxf(v.w, 0.f);
    }
    reinterpret_cast<float4*>(out)[i] = v;
}

// ---------------- edge scatter (vectorized RED) ----------------
__device__ __forceinline__ void red_add_v4(float* ptr, float4 v) {
    asm volatile("red.global.add.v4.f32 [%0], {%1, %2, %3, %4};"
                 :: "l"(ptr), "f"(v.x), "f"(v.y), "f"(v.z), "f"(v.w) : "memory");
}

template <int F4>
__global__ void scatter_kernel(const float* __restrict__ H, const int* __restrict__ src,
                               const int* __restrict__ dst, float* __restrict__ agg,
                               int E, const float* __restrict__ pre) {
    int i = blockIdx.x * blockDim.x + threadIdx.x;
    if (i >= E * F4) return;
    int e = i / F4;
    int c = i % F4;
    int s = src[e];
    int d = dst[e];
    float4 v = reinterpret_cast<const float4*>(H)[(size_t)s * F4 + c];
    if (pre) {
        float p = pre[s];
        v.x *= p; v.y *= p; v.z *= p; v.w *= p;
    }
    red_add_v4(agg + ((size_t)d * F4 + c) * 4, v);
}

// ---------------- mma.sync split-bf16 GEMM ----------------
// C[M,N] = (PRE? diag(pre):I) A[M,K] @ W[K,N]  (+ POST: *post[row]+bias, RELU)
// W given pre-split as Wt_hi/Wt_lo bf16 [N][K]. Error ~2^-15 (Al*Wl dropped).
// CTA: 256 thr, tile 128(M) x 128(N), BK=32. Warp tile 32x64.

__device__ __forceinline__ void mma16816(float* d, const uint32_t* a, uint32_t b0, uint32_t b1) {
    asm("mma.sync.aligned.m16n8k16.row.col.f32.bf16.bf16.f32 "
        "{%0,%1,%2,%3}, {%4,%5,%6,%7}, {%8,%9}, {%0,%1,%2,%3};"
        : "+f"(d[0]), "+f"(d[1]), "+f"(d[2]), "+f"(d[3])
        : "r"(a[0]), "r"(a[1]), "r"(a[2]), "r"(a[3]), "r"(b0), "r"(b1));
}

__device__ __forceinline__ uint32_t lds_u32(const __nv_bfloat16* p) {
    return *reinterpret_cast<const uint32_t*>(p);
}

constexpr int MMA_BK = 32;
constexpr int MMA_LDS = MMA_BK + 8;   // bf16 elems per smem row (pad 16B)

template <bool PRE, bool POST, bool RELU>
__global__ __launch_bounds__(256, 2)
void mgemm_kernel(const float* __restrict__ A,
                  const __nv_bfloat16* __restrict__ Wth,
                  const __nv_bfloat16* __restrict__ Wtl,
                  float* __restrict__ C, int M, int N, int K,
                  const float* __restrict__ pre,
                  const float* __restrict__ post,
                  const float* __restrict__ bias) {
    __shared__ __align__(16) __nv_bfloat16 Ah[128][MMA_LDS];
    __shared__ __align__(16) __nv_bfloat16 Al[128][MMA_LDS];
    __shared__ __align__(16) __nv_bfloat16 Wh[128][MMA_LDS];
    __shared__ __align__(16) __nv_bfloat16 Wl[128][MMA_LDS];

    const int tid = threadIdx.x;
    const int lane = tid & 31;
    const int wid = tid >> 5;
    const int m0 = blockIdx.x * 128;
    const int n0 = blockIdx.y * 128;
    const int wm = (wid & 3) * 32;   // warp row offset in tile
    const int wn = (wid >> 2) * 64;  // warp col offset in tile
    const int g = lane >> 2;         // 0..7
    const int tg2 = (lane & 3) * 2;  // 0,2,4,6

    float acc[2][8][4] = {};

    for (int k0 = 0; k0 < K; k0 += MMA_BK) {
        if (k0 > 0) __syncthreads();
        // --- A chunk: fp32 coalesced load, split hi/lo bf16 into smem ---
        #pragma unroll
        for (int it = 0; it < 4; ++it) {
            int idx = it * 256 + tid;     // 0..1023
            int row = idx >> 3;           // 0..127
            int c4 = idx & 7;             // 0..7 (float4 within 32)
            int gr = m0 + row;
            float4 a = make_float4(0.f, 0.f, 0.f, 0.f);
            if (gr < M) {
                a = *reinterpret_cast<const float4*>(A + (size_t)gr * K + k0 + c4 * 4);
                if (PRE) {
                    float s = pre[gr];
                    a.x *= s; a.y *= s; a.z *= s; a.w *= s;
                }
            }
            __nv_bfloat162 h01 = __floats2bfloat162_rn(a.x, a.y);
            __nv_bfloat162 h23 = __floats2bfloat162_rn(a.z, a.w);
            float l0 = a.x - __bfloat162float(h01.x);
            float l1 = a.y - __bfloat162float(h01.y);
            float l2 = a.z - __bfloat162float(h23.x);
            float l3 = a.w - __bfloat162float(h23.y);
            __nv_bfloat162 lo01 = __floats2bfloat162_rn(l0, l1);
            __nv_bfloat162 lo23 = __floats2bfloat162_rn(l2, l3);
            uint32_t* ph = reinterpret_cast<uint32_t*>(&Ah[row][c4 * 4]);
            uint32_t* pl = reinterpret_cast<uint32_t*>(&Al[row][c4 * 4]);
            ph[0] = *reinterpret_cast<uint32_t*>(&h01);
            ph[1] = *reinterpret_cast<uint32_t*>(&h23);
            pl[0] = *reinterpret_cast<uint32_t*>(&lo01);
            pl[1] = *reinterpret_cast<uint32_t*>(&lo23);
        }
        // --- W chunk: pre-split bf16 [N][K], copy into smem ---
        #pragma unroll
        for (int it = 0; it < 8; ++it) {
            int idx = it * 256 + tid;     // 0..2047
            int n = idx >> 4;             // 0..127
            int ku = idx & 15;            // u32 index within 32 bf16
            int gn = n0 + n;
            uint32_t vh = 0, vl = 0;
            if (gn < N) {
                vh = *reinterpret_cast<const uint32_t*>(Wth + (size_t)gn * K + k0 + ku * 2);
                vl = *reinterpret_cast<const uint32_t*>(Wtl + (size_t)gn * K + k0 + ku * 2);
            }
            reinterpret_cast<uint32_t*>(&Wh[n][0])[ku] = vh;
            reinterpret_cast<uint32_t*>(&Wl[n][0])[ku] = vl;
        }
        __syncthreads();

        // --- 3 passes: Ah*Wh, Ah*Wl, Al*Wh ---
        #pragma unroll
        for (int pass = 0; pass < 3; ++pass) {
            const __nv_bfloat16 (*Asm)[MMA_LDS] = (pass == 2) ? Al : Ah;
            const __nv_bfloat16 (*Wsm)[MMA_LDS] = (pass == 1) ? Wl : Wh;
            #pragma unroll
            for (int ks = 0; ks < MMA_BK / 16; ++ks) {
                int kk = ks * 16;
                uint32_t afr[2][4];
                #pragma unroll
                for (int mi = 0; mi < 2; ++mi) {
                    int r = wm + mi * 16;
                    afr[mi][0] = lds_u32(&Asm[r + g][kk + tg2]);
                    afr[mi][1] = lds_u32(&Asm[r + g + 8][kk + tg2]);
                    afr[mi][2] = lds_u32(&Asm[r + g][kk + tg2 + 8]);
                    afr[mi][3] = lds_u32(&Asm[r + g + 8][kk + tg2 + 8]);
                }
                #pragma unroll
                for (int ni = 0; ni < 8; ++ni) {
                    int n = wn + ni * 8 + g;
                    uint32_t b0 = lds_u32(&Wsm[n][kk + tg2]);
                    uint32_t b1 = lds_u32(&Wsm[n][kk + tg2 + 8]);
                    mma16816(acc[0][ni], afr[0], b0, b1);
                    mma16816(acc[1][ni], afr[1], b0, b1);
                }
            }
        }
    }

    // --- epilogue ---
    #pragma unroll
    for (int mi = 0; mi < 2; ++mi) {
        int r0 = m0 + wm + mi * 16 + g;
        int r1 = r0 + 8;
        float p0 = 1.f, p1 = 1.f;
        if (POST) {
            if (r0 < M) p0 = post[r0];
            if (r1 < M) p1 = post[r1];
        }
        #pragma unroll
        for (int ni = 0; ni < 8; ++ni) {
            int col = n0 + wn + ni * 8 + tg2;
            if (col >= N) continue;
            float bx = 0.f, by = 0.f;
            if (POST) { bx = bias[col]; by = bias[col + 1]; }
            if (r0 < M) {
                float vx = acc[mi][ni][0], vy = acc[mi][ni][1];
                if (POST) { vx = vx * p0 + bx; vy = vy * p0 + by; }
                if (RELU) { vx = fmaxf(vx, 0.f); vy = fmaxf(vy, 0.f); }
                *reinterpret_cast<float2*>(C + (size_t)r0 * N + col) = make_float2(vx, vy);
            }
            if (r1 < M) {
                float vx = acc[mi][ni][2], vy = acc[mi][ni][3];
                if (POST) { vx = vx * p1 + bx; vy = vy * p1 + by; }
                if (RELU) { vx = fmaxf(vx, 0.f); vy = fmaxf(vy, 0.f); }
                *reinterpret_cast<float2*>(C + (size_t)r1 * N + col) = make_float2(vx, vy);
            }
        }
    }
}

// ---------------- launch ----------------
static inline int cdiv(int a, int b) { return (a + b - 1) / b; }

extern "C" void kernel_launch(void* const* d_in, const int* in_sizes, int n_in,
                              void* d_out, int out_size) {
    const float* feat = (const float*)d_in[0];
    const int*   src  = (const int*)d_in[1];
    const int*   dst  = (const int*)d_in[2];
    const float* W1   = (const float*)d_in[3];
    const float* b1   = (const float*)d_in[4];
    const float* W2   = (const float*)d_in[5];
    const float* b2   = (const float*)d_in[6];
    const float* W3   = (const float*)d_in[7];
    const float* b3   = (const float*)d_in[8];
    const int E = in_sizes[1];
    float* out = (float*)d_out;

    float *agg1, *X1, *T2, *agg2, *X2, *T3, *agg3, *outdeg, *indeg, *invout, *invin;
    __nv_bfloat16 *wt1h, *wt1l, *wt2h, *wt2l, *wt3h, *wt3l;
    cudaGetSymbolAddress((void**)&agg1, g_agg1);
    cudaGetSymbolAddress((void**)&X1, g_X1);
    cudaGetSymbolAddress((void**)&T2, g_T2);
    cudaGetSymbolAddress((void**)&agg2, g_agg2);
    cudaGetSymbolAddress((void**)&X2, g_X2);
    cudaGetSymbolAddress((void**)&T3, g_T3);
    cudaGetSymbolAddress((void**)&agg3, g_agg3);
    cudaGetSymbolAddress((void**)&outdeg, g_outdeg);
    cudaGetSymbolAddress((void**)&indeg, g_indeg);
    cudaGetSymbolAddress((void**)&invout, g_invout);
    cudaGetSymbolAddress((void**)&invin, g_invin);
    cudaGetSymbolAddress((void**)&wt1h, g_Wt1h);
    cudaGetSymbolAddress((void**)&wt1l, g_Wt1l);
    cudaGetSymbolAddress((void**)&wt2h, g_Wt2h);
    cudaGetSymbolAddress((void**)&wt2l, g_Wt2l);
    cudaGetSymbolAddress((void**)&wt3h, g_Wt3h);
    cudaGetSymbolAddress((void**)&wt3l, g_Wt3l);

    const int T = 256;
    const int MG = cdiv(NN, 128);  // 782 row tiles

    // zero accumulators + degrees
    zero_all_kernel<<<cdiv(NN * 128, T), T>>>(agg1, agg2, agg3, outdeg, indeg);
    // degree norms
    degree_kernel<<<cdiv(E, T), T>>>(src, dst, outdeg, indeg, E);
    inv_kernel<<<cdiv(NN, T), T>>>(outdeg, indeg, invout, invin, NN);
    // weight transpose+split (tiny)
    wsplit_kernel<<<cdiv(128 * 256, T), T>>>(W1, 128, 256, wt1h, wt1l);
    wsplit_kernel<<<cdiv(256 * 128, T), T>>>(W2, 256, 128, wt2h, wt2l);
    wsplit_kernel<<<cdiv(128 * 40, T), T>>>(W3, 128, 40, wt3h, wt3l);

    // ---- Layer 1: aggregate-first ----
    scatter_kernel<32><<<cdiv(E * 32, T), T>>>(feat, src, dst, agg1, E, invout);
    {
        dim3 grid(MG, 2);
        mgemm_kernel<false, true, true><<<grid, T>>>(agg1, wt1h, wt1l, X1,
                                                     NN, 256, 128, nullptr, invin, b1);
    }

    // ---- Layer 2: transform-first ----
    {
        dim3 grid(MG, 1);
        mgemm_kernel<true, false, false><<<grid, T>>>(X1, wt2h, wt2l, T2,
                                                      NN, 128, 256, invout, nullptr, nullptr);
    }
    scatter_kernel<32><<<cdiv(E * 32, T), T>>>(T2, src, dst, agg2, E, nullptr);
    ew_post_kernel<<<cdiv(NN * 32, T), T>>>(agg2, invin, b2, X2, NN, 32, 1);

    // ---- Layer 3: transform-first ----
    {
        dim3 grid(MG, 1);
        mgemm_kernel<true, false, false><<<grid, T>>>(X2, wt3h, wt3l, T3,
                                                      NN, 40, 128, invout, nullptr, nullptr);
    }
    scatter_kernel<10><<<cdiv(E * 10, T), T>>>(T3, src, dst, agg3, E, nullptr);
    ew_post_kernel<<<cdiv(NN * 10, T), T>>>(agg3, invin, b3, out, NN, 10, 0);
}

// round 5
// speedup vs baseline: 2.0347x; 1.2805x over previous
#include <cuda_runtime.h>
#include <cuda_bf16.h>
#include <cstdint>
#include <cstddef>

#define NN 100000
#define EDGES_MAX 800000

// ---------------- scratch (static __device__, no allocation) ----------------
__device__ __align__(256) float g_agg1[NN * 128];
__device__ __align__(256) float g_X1[(size_t)NN * 256];
__device__ __align__(256) float g_T2[NN * 128];
__device__ __align__(256) float g_X2[NN * 128];
__device__ __align__(256) float g_T3[NN * 40];
__device__ __align__(256) float g_outdeg[NN];
__device__ __align__(256) float g_indeg[NN];
__device__ __align__(256) float g_invout[NN];
__device__ __align__(256) float g_invin[NN];
// CSR (grouped by dst)
__device__ __align__(256) int g_rowinc[NN];
__device__ __align__(256) int g_rowstart[NN];
__device__ __align__(256) int g_ctr[NN];
__device__ __align__(256) int g_blocksum[128];
__device__ __align__(256) int g_csr[EDGES_MAX];
// W^T split-bf16 (hi/lo), layout [N][K] K-contiguous
__device__ __align__(256) __nv_bfloat16 g_Wt1h[256 * 128];
__device__ __align__(256) __nv_bfloat16 g_Wt1l[256 * 128];
__device__ __align__(256) __nv_bfloat16 g_Wt2h[128 * 256];
__device__ __align__(256) __nv_bfloat16 g_Wt2l[128 * 256];
__device__ __align__(256) __nv_bfloat16 g_Wt3h[40 * 128];
__device__ __align__(256) __nv_bfloat16 g_Wt3l[40 * 128];

// ---------------- prep: zero degree arrays + split all weights ----------------
__device__ __forceinline__ void wsplit_one(const float* __restrict__ W, int K, int N, int i,
                                           __nv_bfloat16* __restrict__ th,
                                           __nv_bfloat16* __restrict__ tl) {
    int k = i / N, n = i % N;
    float w = W[i];
    __nv_bfloat16 h = __float2bfloat16(w);
    float r = w - __bfloat162float(h);
    th[n * K + k] = h;
    tl[n * K + k] = __float2bfloat16(r);
}

// NOTE: must be launched with >= NN threads (covers both NN and 128*256 ranges)
__global__ void prep_kernel(const float* __restrict__ W1, const float* __restrict__ W2,
                            const float* __restrict__ W3,
                            __nv_bfloat16* __restrict__ w1h, __nv_bfloat16* __restrict__ w1l,
                            __nv_bfloat16* __restrict__ w2h, __nv_bfloat16* __restrict__ w2l,
                            __nv_bfloat16* __restrict__ w3h, __nv_bfloat16* __restrict__ w3l,
                            float* __restrict__ outdeg, float* __restrict__ indeg) {
    int i = blockIdx.x * blockDim.x + threadIdx.x;
    if (i < NN) { outdeg[i] = 0.0f; indeg[i] = 0.0f; }
    if (i < 128 * 256) {
        wsplit_one(W1, 128, 256, i, w1h, w1l);
        wsplit_one(W2, 256, 128, i, w2h, w2l);
    }
    if (i < 128 * 40) wsplit_one(W3, 128, 40, i, w3h, w3l);
}

__global__ void degree_kernel(const int* __restrict__ src, const int* __restrict__ dst,
                              float* __restrict__ outdeg, float* __restrict__ indeg, int E) {
    int i = blockIdx.x * blockDim.x + threadIdx.x;
    if (i >= E) return;
    atomicAdd(&outdeg[src[i]], 1.0f);
    atomicAdd(&indeg[dst[i]], 1.0f);
}

// ---------------- 3-phase deterministic exclusive scan of indeg ----------------
__global__ __launch_bounds__(1024)
void scan1_kernel(const float* __restrict__ indeg, int* __restrict__ rowinc,
                  int* __restrict__ blocksum, int n) {
    __shared__ int sm[1024];
    int t = threadIdx.x;
    int i = blockIdx.x * 1024 + t;
    int v = (i < n) ? (int)indeg[i] : 0;
    sm[t] = v;
    __syncthreads();
    #pragma unroll
    for (int off = 1; off < 1024; off <<= 1) {
        int a = (t >= off) ? sm[t - off] : 0;
        __syncthreads();
        sm[t] += a;
        __syncthreads();
    }
    if (i < n) rowinc[i] = sm[t];
    if (t == 1023) blocksum[blockIdx.x] = sm[1023];
}

__global__ __launch_bounds__(128)
void scan2_kernel(int* __restrict__ blocksum, int nb) {
    __shared__ int sm[128];
    int t = threadIdx.x;
    int v = (t < nb) ? blocksum[t] : 0;
    sm[t] = v;
    __syncthreads();
    #pragma unroll
    for (int off = 1; off < 128; off <<= 1) {
        int a = (t >= off) ? sm[t - off] : 0;
        __syncthreads();
        sm[t] += a;
        __syncthreads();
    }
    if (t < nb) blocksum[t] = sm[t] - v;   // exclusive
}

__global__ void scan3_kernel(const int* __restrict__ rowinc, const float* __restrict__ indeg,
                             const float* __restrict__ outdeg, const int* __restrict__ blocksum,
                             int* __restrict__ rowstart, int* __restrict__ ctr,
                             float* __restrict__ invout, float* __restrict__ invin, int n) {
    int i = blockIdx.x * blockDim.x + threadIdx.x;
    if (i >= n) return;
    int rs = rowinc[i] - (int)indeg[i] + blocksum[i >> 10];
    rowstart[i] = rs;
    ctr[i] = rs;
    invout[i] = rsqrtf(fmaxf(outdeg[i], 1.0f));
    invin[i]  = rsqrtf(fmaxf(indeg[i], 1.0f));
}

__global__ void fill_kernel(const int* __restrict__ src, const int* __restrict__ dst,
                            int* __restrict__ ctr, int* __restrict__ csr, int E) {
    int i = blockIdx.x * blockDim.x + threadIdx.x;
    if (i >= E) return;
    int p = atomicAdd(&ctr[dst[i]], 1);
    csr[p] = src[i];
}

// ---------------- CSR gather aggregation: one warp per dst node ----------------
// out[w][.] = (relu?) ( sum_{e in in(w)} pre[src]*H[src][.] ) * invin[w] + bias
template <int F4, bool PRE, bool POST, bool RELU>
__global__ __launch_bounds__(256)
void agg_kernel(const float* __restrict__ H, const int* __restrict__ csr,
                const int* __restrict__ rowstart, const float* __restrict__ indeg,
                const float* __restrict__ pre, const float* __restrict__ invin,
                const float* __restrict__ bias, float* __restrict__ out, int n) {
    int w = (blockIdx.x * blockDim.x + threadIdx.x) >> 5;
    if (w >= n) return;
    int lane = threadIdx.x & 31;
    int start = rowstart[w];
    int deg = (int)indeg[w];

    float4 acc = make_float4(0.f, 0.f, 0.f, 0.f);
    const float4* Hv = reinterpret_cast<const float4*>(H);

    for (int base = 0; base < deg; base += 32) {
        int nchunk = min(32, deg - base);
        int idx = 0;
        float pval = 1.0f;
        if (lane < nchunk) {
            idx = csr[start + base + lane];
            if (PRE) pval = pre[idx];
        }
        #pragma unroll 4
        for (int j = 0; j < nchunk; ++j) {
            int s = __shfl_sync(0xffffffffu, idx, j);
            float p = PRE ? __shfl_sync(0xffffffffu, pval, j) : 1.0f;
            if (lane < F4) {
                float4 v = Hv[(size_t)s * F4 + lane];
                if (PRE) {
                    acc.x = fmaf(v.x, p, acc.x);
                    acc.y = fmaf(v.y, p, acc.y);
                    acc.z = fmaf(v.z, p, acc.z);
                    acc.w = fmaf(v.w, p, acc.w);
                } else {
                    acc.x += v.x; acc.y += v.y; acc.z += v.z; acc.w += v.w;
                }
            }
        }
    }

    if (lane < F4) {
        if (POST) {
            float s = invin[w];
            float4 b = reinterpret_cast<const float4*>(bias)[lane];
            acc.x = acc.x * s + b.x;
            acc.y = acc.y * s + b.y;
            acc.z = acc.z * s + b.z;
            acc.w = acc.w * s + b.w;
        }
        if (RELU) {
            acc.x = fmaxf(acc.x, 0.f); acc.y = fmaxf(acc.y, 0.f);
            acc.z = fmaxf(acc.z, 0.f); acc.w = fmaxf(acc.w, 0.f);
        }
        reinterpret_cast<float4*>(out)[(size_t)w * F4 + lane] = acc;
    }
}

// ---------------- mma.sync split-bf16 GEMM ----------------
__device__ __forceinline__ void mma16816(float* d, const uint32_t* a, uint32_t b0, uint32_t b1) {
    asm("mma.sync.aligned.m16n8k16.row.col.f32.bf16.bf16.f32 "
        "{%0,%1,%2,%3}, {%4,%5,%6,%7}, {%8,%9}, {%0,%1,%2,%3};"
        : "+f"(d[0]), "+f"(d[1]), "+f"(d[2]), "+f"(d[3])
        : "r"(a[0]), "r"(a[1]), "r"(a[2]), "r"(a[3]), "r"(b0), "r"(b1));
}

__device__ __forceinline__ uint32_t lds_u32(const __nv_bfloat16* p) {
    return *reinterpret_cast<const uint32_t*>(p);
}

constexpr int MMA_BK = 32;
constexpr int MMA_LDS = MMA_BK + 8;

template <bool PRE, bool POST, bool RELU>
__global__ __launch_bounds__(256, 2)
void mgemm_kernel(const float* __restrict__ A,
                  const __nv_bfloat16* __restrict__ Wth,
                  const __nv_bfloat16* __restrict__ Wtl,
                  float* __restrict__ C, int M, int N, int K,
                  const float* __restrict__ pre,
                  const float* __restrict__ post,
                  const float* __restrict__ bias) {
    __shared__ __align__(16) __nv_bfloat16 Ah[128][MMA_LDS];
    __shared__ __align__(16) __nv_bfloat16 Al[128][MMA_LDS];
    __shared__ __align__(16) __nv_bfloat16 Wh[128][MMA_LDS];
    __shared__ __align__(16) __nv_bfloat16 Wl[128][MMA_LDS];

    const int tid = threadIdx.x;
    const int lane = tid & 31;
    const int wid = tid >> 5;
    const int m0 = blockIdx.x * 128;
    const int n0 = blockIdx.y * 128;
    const int wm = (wid & 3) * 32;
    const int wn = (wid >> 2) * 64;
    const int g = lane >> 2;
    const int tg2 = (lane & 3) * 2;

    float acc[2][8][4] = {};

    for (int k0 = 0; k0 < K; k0 += MMA_BK) {
        if (k0 > 0) __syncthreads();
        #pragma unroll
        for (int it = 0; it < 4; ++it) {
            int idx = it * 256 + tid;
            int row = idx >> 3;
            int c4 = idx & 7;
            int gr = m0 + row;
            float4 a = make_float4(0.f, 0.f, 0.f, 0.f);
            if (gr < M) {
                a = *reinterpret_cast<const float4*>(A + (size_t)gr * K + k0 + c4 * 4);
                if (PRE) {
                    float s = pre[gr];
                    a.x *= s; a.y *= s; a.z *= s; a.w *= s;
                }
            }
            __nv_bfloat162 h01 = __floats2bfloat162_rn(a.x, a.y);
            __nv_bfloat162 h23 = __floats2bfloat162_rn(a.z, a.w);
            float l0 = a.x - __bfloat162float(h01.x);
            float l1 = a.y - __bfloat162float(h01.y);
            float l2 = a.z - __bfloat162float(h23.x);
            float l3 = a.w - __bfloat162float(h23.y);
            __nv_bfloat162 lo01 = __floats2bfloat162_rn(l0, l1);
            __nv_bfloat162 lo23 = __floats2bfloat162_rn(l2, l3);
            uint32_t* ph = reinterpret_cast<uint32_t*>(&Ah[row][c4 * 4]);
            uint32_t* pl = reinterpret_cast<uint32_t*>(&Al[row][c4 * 4]);
            ph[0] = *reinterpret_cast<uint32_t*>(&h01);
            ph[1] = *reinterpret_cast<uint32_t*>(&h23);
            pl[0] = *reinterpret_cast<uint32_t*>(&lo01);
            pl[1] = *reinterpret_cast<uint32_t*>(&lo23);
        }
        #pragma unroll
        for (int it = 0; it < 8; ++it) {
            int idx = it * 256 + tid;
            int n = idx >> 4;
            int ku = idx & 15;
            int gn = n0 + n;
            uint32_t vh = 0, vl = 0;
            if (gn < N) {
                vh = *reinterpret_cast<const uint32_t*>(Wth + (size_t)gn * K + k0 + ku * 2);
                vl = *reinterpret_cast<const uint32_t*>(Wtl + (size_t)gn * K + k0 + ku * 2);
            }
            reinterpret_cast<uint32_t*>(&Wh[n][0])[ku] = vh;
            reinterpret_cast<uint32_t*>(&Wl[n][0])[ku] = vl;
        }
        __syncthreads();

        #pragma unroll
        for (int pass = 0; pass < 3; ++pass) {
            const __nv_bfloat16 (*Asm)[MMA_LDS] = (pass == 2) ? Al : Ah;
            const __nv_bfloat16 (*Wsm)[MMA_LDS] = (pass == 1) ? Wl : Wh;
            #pragma unroll
            for (int ks = 0; ks < MMA_BK / 16; ++ks) {
                int kk = ks * 16;
                uint32_t afr[2][4];
                #pragma unroll
                for (int mi = 0; mi < 2; ++mi) {
                    int r = wm + mi * 16;
                    afr[mi][0] = lds_u32(&Asm[r + g][kk + tg2]);
                    afr[mi][1] = lds_u32(&Asm[r + g + 8][kk + tg2]);
                    afr[mi][2] = lds_u32(&Asm[r + g][kk + tg2 + 8]);
                    afr[mi][3] = lds_u32(&Asm[r + g + 8][kk + tg2 + 8]);
                }
                #pragma unroll
                for (int ni = 0; ni < 8; ++ni) {
                    int n = wn + ni * 8 + g;
                    uint32_t b0 = lds_u32(&Wsm[n][kk + tg2]);
                    uint32_t b1 = lds_u32(&Wsm[n][kk + tg2 + 8]);
                    mma16816(acc[0][ni], afr[0], b0, b1);
                    mma16816(acc[1][ni], afr[1], b0, b1);
                }
            }
        }
    }

    #pragma unroll
    for (int mi = 0; mi < 2; ++mi) {
        int r0 = m0 + wm + mi * 16 + g;
        int r1 = r0 + 8;
        float p0 = 1.f, p1 = 1.f;
        if (POST) {
            if (r0 < M) p0 = post[r0];
            if (r1 < M) p1 = post[r1];
        }
        #pragma unroll
        for (int ni = 0; ni < 8; ++ni) {
            int col = n0 + wn + ni * 8 + tg2;
            if (col >= N) continue;
            float bx = 0.f, by = 0.f;
            if (POST) { bx = bias[col]; by = bias[col + 1]; }
            if (r0 < M) {
                float vx = acc[mi][ni][0], vy = acc[mi][ni][1];
                if (POST) { vx = vx * p0 + bx; vy = vy * p0 + by; }
                if (RELU) { vx = fmaxf(vx, 0.f); vy = fmaxf(vy, 0.f); }
                *reinterpret_cast<float2*>(C + (size_t)r0 * N + col) = make_float2(vx, vy);
            }
            if (r1 < M) {
                float vx = acc[mi][ni][2], vy = acc[mi][ni][3];
                if (POST) { vx = vx * p1 + bx; vy = vy * p1 + by; }
                if (RELU) { vx = fmaxf(vx, 0.f); vy = fmaxf(vy, 0.f); }
                *reinterpret_cast<float2*>(C + (size_t)r1 * N + col) = make_float2(vx, vy);
            }
        }
    }
}

// ---------------- launch ----------------
static inline int cdiv(int a, int b) { return (a + b - 1) / b; }

extern "C" void kernel_launch(void* const* d_in, const int* in_sizes, int n_in,
                              void* d_out, int out_size) {
    const float* feat = (const float*)d_in[0];
    const int*   src  = (const int*)d_in[1];
    const int*   dst  = (const int*)d_in[2];
    const float* W1   = (const float*)d_in[3];
    const float* b1   = (const float*)d_in[4];
    const float* W2   = (const float*)d_in[5];
    const float* b2   = (const float*)d_in[6];
    const float* W3   = (const float*)d_in[7];
    const float* b3   = (const float*)d_in[8];
    const int E = in_sizes[1];
    float* out = (float*)d_out;

    float *agg1, *X1, *T2, *X2, *T3, *outdeg, *indeg, *invout, *invin;
    int *rowinc, *rowstart, *ctr, *blocksum, *csr;
    __nv_bfloat16 *wt1h, *wt1l, *wt2h, *wt2l, *wt3h, *wt3l;
    cudaGetSymbolAddress((void**)&agg1, g_agg1);
    cudaGetSymbolAddress((void**)&X1, g_X1);
    cudaGetSymbolAddress((void**)&T2, g_T2);
    cudaGetSymbolAddress((void**)&X2, g_X2);
    cudaGetSymbolAddress((void**)&T3, g_T3);
    cudaGetSymbolAddress((void**)&outdeg, g_outdeg);
    cudaGetSymbolAddress((void**)&indeg, g_indeg);
    cudaGetSymbolAddress((void**)&invout, g_invout);
    cudaGetSymbolAddress((void**)&invin, g_invin);
    cudaGetSymbolAddress((void**)&rowinc, g_rowinc);
    cudaGetSymbolAddress((void**)&rowstart, g_rowstart);
    cudaGetSymbolAddress((void**)&ctr, g_ctr);
    cudaGetSymbolAddress((void**)&blocksum, g_blocksum);
    cudaGetSymbolAddress((void**)&csr, g_csr);
    cudaGetSymbolAddress((void**)&wt1h, g_Wt1h);
    cudaGetSymbolAddress((void**)&wt1l, g_Wt1l);
    cudaGetSymbolAddress((void**)&wt2h, g_Wt2h);
    cudaGetSymbolAddress((void**)&wt2l, g_Wt2l);
    cudaGetSymbolAddress((void**)&wt3h, g_Wt3h);
    cudaGetSymbolAddress((void**)&wt3l, g_Wt3l);

    const int T = 256;
    const int MG = cdiv(NN, 128);
    const int AGG_GRID = cdiv(NN, 8);   // 8 warps/block, warp per node
    const int NB = cdiv(NN, 1024);

    // 0: prep (zero degrees + split weights) — MUST cover NN threads
    prep_kernel<<<cdiv(NN, T), T>>>(W1, W2, W3, wt1h, wt1l, wt2h, wt2l,
                                    wt3h, wt3l, outdeg, indeg);
    // 1: degree histogram
    degree_kernel<<<cdiv(E, T), T>>>(src, dst, outdeg, indeg, E);
    // 2-4: deterministic scan -> rowstart/ctr (+ inv norms)
    scan1_kernel<<<NB, 1024>>>(indeg, rowinc, blocksum, NN);
    scan2_kernel<<<1, 128>>>(blocksum, NB);
    scan3_kernel<<<cdiv(NN, T), T>>>(rowinc, indeg, outdeg, blocksum,
                                     rowstart, ctr, invout, invin, NN);
    // 5: CSR fill
    fill_kernel<<<cdiv(E, T), T>>>(src, dst, ctr, csr, E);

    // ---- Layer 1: aggregate-first ----
    agg_kernel<32, true, false, false><<<AGG_GRID, T>>>(
        feat, csr, rowstart, indeg, invout, nullptr, nullptr, agg1, NN);
    {
        dim3 grid(MG, 2);
        mgemm_kernel<false, true, true><<<grid, T>>>(agg1, wt1h, wt1l, X1,
                                                     NN, 256, 128, nullptr, invin, b1);
    }

    // ---- Layer 2: transform-first ----
    {
        dim3 grid(MG, 1);
        mgemm_kernel<true, false, false><<<grid, T>>>(X1, wt2h, wt2l, T2,
                                                      NN, 128, 256, invout, nullptr, nullptr);
    }
    agg_kernel<32, false, true, true><<<AGG_GRID, T>>>(
        T2, csr, rowstart, indeg, nullptr, invin, b2, X2, NN);

    // ---- Layer 3: transform-first ----
    {
        dim3 grid(MG, 1);
        mgemm_kernel<true, false, false><<<grid, T>>>(X2, wt3h, wt3l, T3,
                                                      NN, 40, 128, invout, nullptr, nullptr);
    }
    agg_kernel<10, false, true, false><<<AGG_GRID, T>>>(
        T3, csr, rowstart, indeg, nullptr, invin, b3, out, NN);
}